// round 1
// baseline (speedup 1.0000x reference)
#include <cuda_runtime.h>
#include <cstddef>

// CSPN_6468220748336
// out[b,y,x] = sum_{i,j in [0,7)} gw[b, i*7+j, y+3, x+3] * src[b, y+3-i, x+3-j]
//   src = h0 when (i,j)==(3,3), else hn; zero outside [0,512)^2.
// Inputs (metadata order): guide_weight f32 (8,49,518,518), hn f32 (8,1,512,512), h0 f32 (8,1,512,512)
// Output: f32 (8,1,512,512)

namespace {
constexpr int K  = 7;
constexpr int K2 = 49;
constexpr int B  = 8;
constexpr int H  = 512;
constexpr int W  = 512;
constexpr int HP = H + K - 1;   // 518
constexpr int WP = W + K - 1;   // 518

constexpr int TX = 32;          // tile width  (threads x)
constexpr int TY = 8;           // tile height (threads y)
constexpr int SW = TX + K - 1;  // 38 shared tile cols
constexpr int SH = TY + K - 1;  // 14 shared tile rows
constexpr int SPITCH = 40;      // padded row stride (avoid conflicts)
}

__global__ __launch_bounds__(TX * TY) void cspn_kernel(
    const float* __restrict__ gw,
    const float* __restrict__ hn,
    const float* __restrict__ h0,
    float* __restrict__ out)
{
    __shared__ float s_hn[SH][SPITCH];

    const int b  = blockIdx.z;
    const int x0 = blockIdx.x * TX;
    const int y0 = blockIdx.y * TY;
    const int tx = threadIdx.x;
    const int ty = threadIdx.y;
    const int tid = ty * TX + tx;

    // --- stage hn halo tile into shared memory (zero-padded at image edges) ---
    const float* __restrict__ hn_b = hn + (size_t)b * H * W;
    #pragma unroll
    for (int idx = tid; idx < SH * SW; idx += TX * TY) {
        const int r  = idx / SW;
        const int c  = idx - r * SW;
        const int gy = y0 - 3 + r;
        const int gx = x0 - 3 + c;
        float v = 0.0f;
        if (gy >= 0 && gy < H && gx >= 0 && gx < W)
            v = __ldg(&hn_b[(size_t)gy * W + gx]);
        s_hn[r][c] = v;
    }
    __syncthreads();

    const int y = y0 + ty;
    const int x = x0 + tx;

    const float h0v = __ldg(&h0[((size_t)b * H + y) * W + x]);

    // gw pointer for tap 0 at this pixel; taps are HP*WP apart.
    const float* __restrict__ gwp =
        gw + (size_t)b * K2 * HP * WP + (size_t)(y + 3) * WP + (x + 3);

    float acc = 0.0f;
    #pragma unroll
    for (int i = 0; i < K; ++i) {
        #pragma unroll
        for (int j = 0; j < K; ++j) {
            // Streaming load: gw is touched exactly once — keep it out of the cache.
            const float w = __ldcs(gwp + (size_t)(i * K + j) * (HP * WP));
            const float v = (i == 3 && j == 3) ? h0v : s_hn[ty + 6 - i][tx + 6 - j];
            acc = fmaf(w, v, acc);
        }
    }

    out[((size_t)b * H + y) * W + x] = acc;
}

extern "C" void kernel_launch(void* const* d_in, const int* in_sizes, int n_in,
                              void* d_out, int out_size)
{
    const float* gw = (const float*)d_in[0];
    const float* hn = (const float*)d_in[1];
    const float* h0 = (const float*)d_in[2];
    float* out = (float*)d_out;

    dim3 block(TX, TY, 1);
    dim3 grid(W / TX, H / TY, B);
    cspn_kernel<<<grid, block>>>(gw, hn, h0, out);
}